// round 1
// baseline (speedup 1.0000x reference)
#include <cuda_runtime.h>
#include <math.h>
#include <stdint.h>

// Problem constants (fixed shapes from setup_inputs)
#define NB   64
#define NC   64          // embedding dim D
#define NH   32
#define NW   32
#define HW   1024        // NH*NW
#define NPTS 65536       // NB*HW
#define KC   1024        // number of codes
#define NELEM 4194304    // NB*NC*HW

#define PITCH 68         // smem pitch (floats): 16B-aligned rows, conflict-light transpose

__device__ float  g_se[KC];
__device__ int    g_idx[NPTS];
__device__ int    g_hist[KC];
__device__ double g_sumsq;

// ---- Blackwell packed fp32x2 helpers (PTX-only, per SASS_QUICKREF) ----
__device__ __forceinline__ unsigned long long fma2(unsigned long long a,
                                                   unsigned long long b,
                                                   unsigned long long c) {
    unsigned long long r;
    asm("fma.rn.f32x2 %0, %1, %2, %3;" : "=l"(r) : "l"(a), "l"(b), "l"(c));
    return r;
}
__device__ __forceinline__ unsigned long long pack2(float x) {
    unsigned long long r;
    asm("mov.b64 %0, {%1, %1};" : "=l"(r) : "f"(x));
    return r;
}
__device__ __forceinline__ void unpack2(unsigned long long v, float& lo, float& hi) {
    asm("mov.b64 {%0, %1}, %2;" : "=f"(lo), "=f"(hi) : "l"(v));
}

// ---- init: zero histogram + loss accumulator (must run every graph replay) ----
__global__ void init_kernel() {
    int t = blockIdx.x * 256 + threadIdx.x;
    if (t < KC) g_hist[t] = 0;
    if (t == 0) g_sumsq = 0.0;
}

// ---- se[k] = sum_d e[k][d]^2 ----
__global__ void __launch_bounds__(256) se_kernel(const float* __restrict__ emb) {
    int k = blockIdx.x * 256 + threadIdx.x;   // grid 4 -> 1024
    const float4* r = (const float4*)(emb + (size_t)k * NC);
    float s = 0.f;
#pragma unroll
    for (int i = 0; i < 16; ++i) {
        float4 v = r[i];
        s += v.x * v.x + v.y * v.y + v.z * v.z + v.w * v.w;
    }
    g_se[k] = s;
}

// ---- distance + argmin kernel ----
// Block: 64 points x all 1024 codes (16 chunks of 64). 256 threads.
// Thread tile: 2 points x 8 codes, packed fp32x2 accumulators (pairs over codes).
__global__ void __launch_bounds__(256) vq_kernel(const float* __restrict__ x,
                                                 const float* __restrict__ emb) {
    __shared__ float xs[64 * PITCH];
    __shared__ float es[64 * PITCH];
    __shared__ float sxs[64];
    __shared__ float ses[64];

    const int tid = threadIdx.x;
    const int tx  = tid & 7;    // code-group (8 codes each)
    const int ty  = tid >> 3;   // point-pair (2 points each, 32 pairs = 64 points)

    const int b   = blockIdx.x >> 4;
    const int hw0 = (blockIdx.x & 15) << 6;
    const float* xb = x + ((size_t)b << 16) + hw0;

    // Load x tile: naturally lands as [d][p] (coalesced, conflict-free)
#pragma unroll
    for (int i = tid; i < 4096; i += 256) {
        int d = i >> 6, p = i & 63;
        xs[d * PITCH + p] = xb[d * HW + p];
    }
    __syncthreads();

    // ||x||^2 per point
    if (tid < 64) {
        float s = 0.f;
#pragma unroll
        for (int d = 0; d < 64; ++d) {
            float v = xs[d * PITCH + tid];
            s = fmaf(v, v, s);
        }
        sxs[tid] = s;
    }

    float bd0 = 3.4e38f, bd1 = 3.4e38f;
    int   bk0 = 0,       bk1 = 0;

    for (int kc = 0; kc < 16; ++kc) {
        __syncthreads();
        // Load 64-code chunk, transposed to [d][c] (stride-68 writes: 4-way max)
        const float* eb = emb + ((size_t)kc << 12);
#pragma unroll
        for (int i = tid; i < 4096; i += 256) {
            int c = i >> 6, d = i & 63;
            es[d * PITCH + c] = eb[i];
        }
        if (tid < 64) ses[tid] = g_se[(kc << 6) + tid];
        __syncthreads();

        unsigned long long acc[8];
#pragma unroll
        for (int j = 0; j < 8; ++j) acc[j] = 0ULL;

#pragma unroll
        for (int d = 0; d < 64; ++d) {
            float2 xv = *(const float2*)&xs[d * PITCH + (ty << 1)];
            ulonglong2 e01 = *(const ulonglong2*)&es[d * PITCH + (tx << 3)];
            ulonglong2 e23 = *(const ulonglong2*)&es[d * PITCH + (tx << 3) + 4];
            unsigned long long x0 = pack2(xv.x);
            unsigned long long x1 = pack2(xv.y);
            acc[0] = fma2(x0, e01.x, acc[0]);
            acc[1] = fma2(x0, e01.y, acc[1]);
            acc[2] = fma2(x0, e23.x, acc[2]);
            acc[3] = fma2(x0, e23.y, acc[3]);
            acc[4] = fma2(x1, e01.x, acc[4]);
            acc[5] = fma2(x1, e01.y, acc[5]);
            acc[6] = fma2(x1, e23.x, acc[6]);
            acc[7] = fma2(x1, e23.y, acc[7]);
        }

        const float sx0 = sxs[(ty << 1)];
        const float sx1 = sxs[(ty << 1) + 1];
        const int   cbase = (kc << 6) + (tx << 3);
#pragma unroll
        for (int j = 0; j < 4; ++j) {
            float d0a, d0b, d1a, d1b;
            unpack2(acc[j],     d0a, d0b);   // point0, codes 2j, 2j+1
            unpack2(acc[4 + j], d1a, d1b);   // point1
            float se_a = ses[(tx << 3) + (j << 1)];
            float se_b = ses[(tx << 3) + (j << 1) + 1];
            int ca = cbase + (j << 1), cb = ca + 1;
            // match reference fp32 order: (sx - 2*dot) + se  (no FMA contraction)
            float da = __fadd_rn(__fsub_rn(sx0, __fmul_rn(2.f, d0a)), se_a);
            if (da < bd0) { bd0 = da; bk0 = ca; }
            float db = __fadd_rn(__fsub_rn(sx0, __fmul_rn(2.f, d0b)), se_b);
            if (db < bd0) { bd0 = db; bk0 = cb; }
            float dc = __fadd_rn(__fsub_rn(sx1, __fmul_rn(2.f, d1a)), se_a);
            if (dc < bd1) { bd1 = dc; bk1 = ca; }
            float dd = __fadd_rn(__fsub_rn(sx1, __fmul_rn(2.f, d1b)), se_b);
            if (dd < bd1) { bd1 = dd; bk1 = cb; }
        }
    }

    // Reduce across the 8 code-group threads (lanes tx=0..7 within warp groups)
#pragma unroll
    for (int off = 4; off; off >>= 1) {
        float od0 = __shfl_xor_sync(0xffffffffu, bd0, off);
        int   ok0 = __shfl_xor_sync(0xffffffffu, bk0, off);
        if (od0 < bd0 || (od0 == bd0 && ok0 < bk0)) { bd0 = od0; bk0 = ok0; }
        float od1 = __shfl_xor_sync(0xffffffffu, bd1, off);
        int   ok1 = __shfl_xor_sync(0xffffffffu, bk1, off);
        if (od1 < bd1 || (od1 == bd1 && ok1 < bk1)) { bd1 = od1; bk1 = ok1; }
    }

    if (tx == 0) {
        int n0 = (blockIdx.x << 6) + (ty << 1);
        g_idx[n0]     = bk0;
        g_idx[n0 + 1] = bk1;
        atomicAdd(&g_hist[bk0], 1);
        atomicAdd(&g_hist[bk1], 1);
    }
}

// ---- gather to NCHW + fused sum of squared diffs ----
__global__ void __launch_bounds__(256) gather_kernel(const float* __restrict__ x,
                                                     const float* __restrict__ emb,
                                                     float* __restrict__ out) {
    int t = blockIdx.x * 256 + threadIdx.x;   // 1048576 threads, 4 elems each
    int l = t << 2;
    int b  = l >> 16;
    int c  = (l >> 10) & 63;
    int hw = l & 1023;
    const int* ip = g_idx + (b << 10) + hw;
    float4 q;
    q.x = emb[ip[0] * NC + c];
    q.y = emb[ip[1] * NC + c];
    q.z = emb[ip[2] * NC + c];
    q.w = emb[ip[3] * NC + c];
    float4 xv = *(const float4*)(x + l);
    *(float4*)(out + l) = q;

    float dx = q.x - xv.x, dy = q.y - xv.y, dz = q.z - xv.z, dw = q.w - xv.w;
    float s = dx * dx + dy * dy + dz * dz + dw * dw;
#pragma unroll
    for (int off = 16; off; off >>= 1) s += __shfl_xor_sync(0xffffffffu, s, off);
    if ((threadIdx.x & 31) == 0) atomicAdd(&g_sumsq, (double)s);
}

// ---- loss + perplexity ----
__global__ void __launch_bounds__(1024) final_kernel(float* __restrict__ out, int nq) {
    __shared__ float red[32];
    int t = threadIdx.x;
    float p = (float)g_hist[t] * (1.0f / 65536.0f);
    float term = p * logf(p + 1e-10f);
#pragma unroll
    for (int off = 16; off; off >>= 1) term += __shfl_xor_sync(0xffffffffu, term, off);
    if ((t & 31) == 0) red[t >> 5] = term;
    __syncthreads();
    if (t < 32) {
        float v = red[t];
#pragma unroll
        for (int off = 16; off; off >>= 1) v += __shfl_xor_sync(0xffffffffu, v, off);
        if (t == 0) {
            float m = (float)(g_sumsq * (1.0 / (double)NELEM));
            out[nq]     = 1.25f * m;   // q_latent + 0.25*e_latent (numerically equal terms)
            out[nq + 1] = expf(-v);
        }
    }
}

extern "C" void kernel_launch(void* const* d_in, const int* in_sizes, int n_in,
                              void* d_out, int out_size) {
    const float* x   = (const float*)d_in[0];
    const float* emb = (const float*)d_in[1];
    if (n_in >= 2 && in_sizes[0] == KC * NC && in_sizes[1] == NELEM) {
        // defensive: inputs arrived swapped
        const float* tmp = x; x = emb; emb = tmp;
    }
    float* out = (float*)d_out;
    int nq = out_size - 2;   // [quantized..., loss, perplexity]

    init_kernel<<<4, 256>>>();
    se_kernel<<<4, 256>>>(emb);
    vq_kernel<<<NPTS / 64, 256>>>(x, emb);
    gather_kernel<<<NELEM / 1024, 256>>>(x, emb, out);
    final_kernel<<<1, 1024>>>(out, nq);
}

// round 3
// speedup vs baseline: 2.8340x; 2.8340x over previous
#include <cuda_runtime.h>
#include <math.h>
#include <stdint.h>

#define NB   64
#define NC   64
#define HW   1024
#define NPTS 65536
#define KC   1024
#define NELEM 4194304

__device__ float  g_et[NC * KC];     // transposed embeddings [d][c]
__device__ float  g_se[KC];
__device__ int    g_idx[NPTS];
__device__ int    g_hist[KC];
__device__ double g_sumsq;

// ---- packed fp32x2 helpers ----
__device__ __forceinline__ unsigned long long fma2(unsigned long long a,
                                                   unsigned long long b,
                                                   unsigned long long c) {
    unsigned long long r;
    asm("fma.rn.f32x2 %0, %1, %2, %3;" : "=l"(r) : "l"(a), "l"(b), "l"(c));
    return r;
}
__device__ __forceinline__ unsigned long long pack2(float x) {
    unsigned long long r;
    asm("mov.b64 %0, {%1, %1};" : "=l"(r) : "f"(x));
    return r;
}
__device__ __forceinline__ void unpack2(unsigned long long v, float& lo, float& hi) {
    asm("mov.b64 {%0, %1}, %2;" : "=f"(lo), "=f"(hi) : "l"(v));
}
__device__ __forceinline__ uint32_t smem_u32(const void* p) {
    uint32_t a;
    asm("{ .reg .u64 t; cvta.to.shared.u64 t, %1; cvt.u32.u64 %0, t; }" : "=r"(a) : "l"(p));
    return a;
}
__device__ __forceinline__ void cpa16(uint32_t dst, const float* src) {
    asm volatile("cp.async.ca.shared.global [%0], [%1], 16;" :: "r"(dst), "l"(src));
}
__device__ __forceinline__ void cpa_commit() { asm volatile("cp.async.commit_group;"); }
__device__ __forceinline__ void cpa_wait1()  { asm volatile("cp.async.wait_group 1;"); }

// ---- prep: transpose emb -> g_et, compute se, zero hist/sumsq ----
__global__ void __launch_bounds__(256) prep_kernel(const float* __restrict__ emb) {
    __shared__ float t[32][33];
    int tid = threadIdx.x;
    int bc = blockIdx.x & 31;      // code tile (32 tiles of 32 codes)
    int bdd = blockIdx.x >> 5;     // d tile (2 tiles of 32)
    int lx = tid & 31, ly = tid >> 5;
#pragma unroll
    for (int r = 0; r < 4; ++r) {
        int c = bc * 32 + ly + r * 8;
        t[ly + r * 8][lx] = emb[c * NC + bdd * 32 + lx];
    }
    __syncthreads();
#pragma unroll
    for (int r = 0; r < 4; ++r) {
        int d = bdd * 32 + ly + r * 8;
        g_et[d * KC + bc * 32 + lx] = t[lx][ly + r * 8];
    }
    int gid = blockIdx.x * 256 + tid;
    if (gid < KC) {
        g_hist[gid] = 0;
        const float4* r4 = (const float4*)(emb + gid * NC);
        float s = 0.f;
#pragma unroll
        for (int i = 0; i < 16; ++i) {
            float4 v = r4[i];
            s += v.x * v.x + v.y * v.y + v.z * v.z + v.w * v.w;
        }
        g_se[gid] = s;
    }
    if (gid == 0) g_sumsq = 0.0;
}

// ---- vq: 128 points x 1024 codes per block, 8x8 thread tile, cp.async pipelined ----
// dyn smem layout (floats): xs[8192] | es0[8192] | es1[8192] | ses[256] | sxs[128]
#define SM_XS   0
#define SM_ES0  8192
#define SM_ES1  16384
#define SM_SES  24576
#define SM_SXS  24832
#define SM_FLOATS 24960

__global__ void __launch_bounds__(256) vq_kernel(const float* __restrict__ x) {
    extern __shared__ float sm[];
    const uint32_t smb = smem_u32(sm);
    const int tid = threadIdx.x;
    const int tx = tid & 15;          // 16 code groups x 8 codes = 128 codes/chunk
    const int ty = tid >> 4;          // 16 point groups x 8 pts = 128 pts
    const int bb  = blockIdx.x >> 3;
    const int hw0 = (blockIdx.x & 7) << 7;
    const float* xb = x + ((size_t)bb << 16) + hw0;

    // prologue: full x tile + chunk0 in group 0; chunk1 in group 1
    {
#pragma unroll
        for (int q = 0; q < 8; ++q) {
            int l = (q * 256 + tid) * 4;               // float offset in [64][128]
            cpa16(smb + (SM_XS + l) * 4, xb + (l >> 7) * HW + (l & 127));
        }
#pragma unroll
        for (int q = 0; q < 8; ++q) {
            int l = (q * 256 + tid) * 4;
            cpa16(smb + (SM_ES0 + l) * 4, g_et + (l >> 7) * KC + (l & 127));
        }
        if (tid < 32) cpa16(smb + (SM_SES + tid * 4) * 4, g_se + tid * 4);
        cpa_commit();
#pragma unroll
        for (int q = 0; q < 8; ++q) {
            int l = (q * 256 + tid) * 4;
            cpa16(smb + (SM_ES1 + l) * 4, g_et + (l >> 7) * KC + 128 + (l & 127));
        }
        if (tid < 32) cpa16(smb + (SM_SES + 128 + tid * 4) * 4, g_se + 128 + tid * 4);
        cpa_commit();
    }
    cpa_wait1();
    __syncthreads();

    // ||x||^2 per point (sequential over d, matches reference order closely enough)
    if (tid < 128) {
        float s = 0.f;
#pragma unroll
        for (int d = 0; d < 64; ++d) {
            float v = sm[SM_XS + d * 128 + tid];
            s = fmaf(v, v, s);
        }
        sm[SM_SXS + tid] = s;
    }
    __syncthreads();

    float sx[8];
#pragma unroll
    for (int p = 0; p < 8; ++p) sx[p] = sm[SM_SXS + (ty << 3) + p];

    float bd[8];
    int   bk[8];
#pragma unroll
    for (int p = 0; p < 8; ++p) { bd[p] = 3.4e38f; bk[p] = 0; }

    for (int kc = 0; kc < 8; ++kc) {
        const int buf = kc & 1;
        const float* eb = sm + (buf ? SM_ES1 : SM_ES0);
        const float* sesb = sm + SM_SES + buf * 128;

        unsigned long long acc[8][4];
#pragma unroll
        for (int p = 0; p < 8; ++p)
#pragma unroll
            for (int j = 0; j < 4; ++j) acc[p][j] = 0ULL;

#pragma unroll 8
        for (int d = 0; d < 64; ++d) {
            const float* xr = sm + SM_XS + d * 128 + (ty << 3);
            float4 xa = *(const float4*)xr;
            float4 xc = *(const float4*)(xr + 4);
            unsigned long long xp[8];
            xp[0] = pack2(xa.x); xp[1] = pack2(xa.y);
            xp[2] = pack2(xa.z); xp[3] = pack2(xa.w);
            xp[4] = pack2(xc.x); xp[5] = pack2(xc.y);
            xp[6] = pack2(xc.z); xp[7] = pack2(xc.w);
            const ulonglong2* er = (const ulonglong2*)(eb + d * 128 + (tx << 3));
            ulonglong2 e01 = er[0];
            ulonglong2 e23 = er[1];
#pragma unroll
            for (int p = 0; p < 8; ++p) {
                acc[p][0] = fma2(xp[p], e01.x, acc[p][0]);
                acc[p][1] = fma2(xp[p], e01.y, acc[p][1]);
                acc[p][2] = fma2(xp[p], e23.x, acc[p][2]);
                acc[p][3] = fma2(xp[p], e23.y, acc[p][3]);
            }
        }

        // epilogue: distance + running argmin (exact reference fp32 order)
        const int cb = (kc << 7) + (tx << 3);
#pragma unroll
        for (int p = 0; p < 8; ++p) {
#pragma unroll
            for (int j = 0; j < 4; ++j) {
                float da, db;
                unpack2(acc[p][j], da, db);
                float sea = sesb[(tx << 3) + 2 * j];
                float seb = sesb[(tx << 3) + 2 * j + 1];
                float va = __fadd_rn(__fsub_rn(sx[p], __fmul_rn(2.f, da)), sea);
                if (va < bd[p]) { bd[p] = va; bk[p] = cb + 2 * j; }
                float vb = __fadd_rn(__fsub_rn(sx[p], __fmul_rn(2.f, db)), seb);
                if (vb < bd[p]) { bd[p] = vb; bk[p] = cb + 2 * j + 1; }
            }
        }

        __syncthreads();          // everyone done reading buf
        if (kc + 2 < 8) {
            const int c0 = (kc + 2) << 7;
#pragma unroll
            for (int q = 0; q < 8; ++q) {
                int l = (q * 256 + tid) * 4;
                cpa16(smb + ((buf ? SM_ES1 : SM_ES0) + l) * 4,
                      g_et + (l >> 7) * KC + c0 + (l & 127));
            }
            if (tid < 32) cpa16(smb + (SM_SES + buf * 128 + tid * 4) * 4, g_se + c0 + tid * 4);
        }
        cpa_commit();
        if (kc < 7) { cpa_wait1(); __syncthreads(); }
    }

    // reduce over the 16 code-group lanes (bits 0..3 of lane id)
#pragma unroll
    for (int off = 1; off < 16; off <<= 1) {
#pragma unroll
        for (int p = 0; p < 8; ++p) {
            float od = __shfl_xor_sync(0xffffffffu, bd[p], off);
            int   ok = __shfl_xor_sync(0xffffffffu, bk[p], off);
            if (od < bd[p] || (od == bd[p] && ok < bk[p])) { bd[p] = od; bk[p] = ok; }
        }
    }
    if (tx == 0) {
        int n0 = (bb << 10) + hw0 + (ty << 3);
#pragma unroll
        for (int p = 0; p < 8; ++p) {
            g_idx[n0 + p] = bk[p];
            atomicAdd(&g_hist[bk[p]], 1);
        }
    }
}

// ---- gather: 64 points x 64 channels per block, smem transpose, coalesced out ----
__global__ void __launch_bounds__(256) gather_kernel(const float* __restrict__ x,
                                                     const float* __restrict__ emb,
                                                     float* __restrict__ out) {
    __shared__ int   sidx[64];
    __shared__ float qs[64 * 65];
    __shared__ float red[8];
    const int tid = threadIdx.x;
    const int bb  = blockIdx.x >> 4;
    const int hw0 = (blockIdx.x & 15) << 6;

    if (tid < 64) sidx[tid] = g_idx[(bb << 10) + hw0 + tid];
    __syncthreads();

    // coalesced embedding row copies -> transposed smem
    {
        int p = tid >> 2, i = tid & 3;
        const float4* er = (const float4*)(emb + (size_t)sidx[p] * NC) + i * 4;
#pragma unroll
        for (int k = 0; k < 4; ++k) {
            float4 v = er[k];
            int d = i * 16 + k * 4;
            qs[p * 65 + d]     = v.x;
            qs[p * 65 + d + 1] = v.y;
            qs[p * 65 + d + 2] = v.z;
            qs[p * 65 + d + 3] = v.w;
        }
    }
    __syncthreads();

    const int lane = tid & 31, w = tid >> 5;
    float s = 0.f;
#pragma unroll
    for (int c8 = 0; c8 < 8; ++c8) {
        int c = w * 8 + c8;
        size_t ob = (((size_t)bb << 6) + c) * HW + hw0;
#pragma unroll
        for (int ph = 0; ph < 2; ++ph) {
            int p = ph * 32 + lane;
            float q  = qs[p * 65 + c];
            float xv = x[ob + p];
            out[ob + p] = q;
            float d = q - xv;
            s = fmaf(d, d, s);
        }
    }
#pragma unroll
    for (int off = 16; off; off >>= 1) s += __shfl_xor_sync(0xffffffffu, s, off);
    if (lane == 0) red[w] = s;
    __syncthreads();
    if (tid == 0) {
        float t = 0.f;
#pragma unroll
        for (int i = 0; i < 8; ++i) t += red[i];
        atomicAdd(&g_sumsq, (double)t);
    }
}

// ---- loss + perplexity ----
__global__ void __launch_bounds__(1024) final_kernel(float* __restrict__ out, int nq) {
    __shared__ float red[32];
    int t = threadIdx.x;
    float p = (float)g_hist[t] * (1.0f / 65536.0f);
    float term = p * logf(p + 1e-10f);
#pragma unroll
    for (int off = 16; off; off >>= 1) term += __shfl_xor_sync(0xffffffffu, term, off);
    if ((t & 31) == 0) red[t >> 5] = term;
    __syncthreads();
    if (t < 32) {
        float v = red[t];
#pragma unroll
        for (int off = 16; off; off >>= 1) v += __shfl_xor_sync(0xffffffffu, v, off);
        if (t == 0) {
            float m = (float)(g_sumsq * (1.0 / (double)NELEM));
            out[nq]     = 1.25f * m;
            out[nq + 1] = expf(-v);
        }
    }
}

extern "C" void kernel_launch(void* const* d_in, const int* in_sizes, int n_in,
                              void* d_out, int out_size) {
    const float* x   = (const float*)d_in[0];
    const float* emb = (const float*)d_in[1];
    if (n_in >= 2 && in_sizes[0] == KC * NC && in_sizes[1] == NELEM) {
        const float* tmp = x; x = emb; emb = tmp;
    }
    float* out = (float*)d_out;
    int nq = out_size - 2;

    cudaFuncSetAttribute(vq_kernel, cudaFuncAttributeMaxDynamicSharedMemorySize,
                         SM_FLOATS * 4);

    prep_kernel<<<64, 256>>>(emb);
    vq_kernel<<<512, 256, SM_FLOATS * 4>>>(x);
    gather_kernel<<<NPTS / 64, 256>>>(x, emb, out);
    final_kernel<<<1, 1024>>>(out, nq);
}

// round 4
// speedup vs baseline: 2.9237x; 1.0316x over previous
#include <cuda_runtime.h>
#include <math.h>
#include <stdint.h>

#define NB   64
#define NC   64
#define HW   1024
#define NPTS 65536
#define KC   1024
#define NELEM 4194304

__device__ float  g_et[NC * KC];     // transposed embeddings [d][c]
__device__ float  g_se[KC];
__device__ int    g_hist[KC];
__device__ double g_sumsq;

// ---- packed fp32x2 helpers ----
__device__ __forceinline__ unsigned long long fma2(unsigned long long a,
                                                   unsigned long long b,
                                                   unsigned long long c) {
    unsigned long long r;
    asm("fma.rn.f32x2 %0, %1, %2, %3;" : "=l"(r) : "l"(a), "l"(b), "l"(c));
    return r;
}
__device__ __forceinline__ unsigned long long pack2(float x) {
    unsigned long long r;
    asm("mov.b64 %0, {%1, %1};" : "=l"(r) : "f"(x));
    return r;
}
__device__ __forceinline__ void unpack2(unsigned long long v, float& lo, float& hi) {
    asm("mov.b64 {%0, %1}, %2;" : "=f"(lo), "=f"(hi) : "l"(v));
}
__device__ __forceinline__ uint32_t smem_u32(const void* p) {
    uint32_t a;
    asm("{ .reg .u64 t; cvta.to.shared.u64 t, %1; cvt.u32.u64 %0, t; }" : "=r"(a) : "l"(p));
    return a;
}
__device__ __forceinline__ void cpa16(uint32_t dst, const float* src) {
    asm volatile("cp.async.ca.shared.global [%0], [%1], 16;" :: "r"(dst), "l"(src));
}
__device__ __forceinline__ void cpa_commit() { asm volatile("cp.async.commit_group;"); }
__device__ __forceinline__ void cpa_wait1()  { asm volatile("cp.async.wait_group 1;"); }

// ---- prep: transpose emb -> g_et, compute se, zero hist/sumsq ----
__global__ void __launch_bounds__(256) prep_kernel(const float* __restrict__ emb) {
    __shared__ float t[32][33];
    int tid = threadIdx.x;
    int bc = blockIdx.x & 31;      // code tile (32 tiles of 32 codes)
    int bdd = blockIdx.x >> 5;     // d tile (2 tiles of 32)
    int lx = tid & 31, ly = tid >> 5;
#pragma unroll
    for (int r = 0; r < 4; ++r) {
        int c = bc * 32 + ly + r * 8;
        t[ly + r * 8][lx] = emb[c * NC + bdd * 32 + lx];
    }
    __syncthreads();
#pragma unroll
    for (int r = 0; r < 4; ++r) {
        int d = bdd * 32 + ly + r * 8;
        g_et[d * KC + bc * 32 + lx] = t[lx][ly + r * 8];
    }
    int gid = blockIdx.x * 256 + tid;
    if (gid < KC) {
        g_hist[gid] = 0;
        const float4* r4 = (const float4*)(emb + gid * NC);
        float s = 0.f;
#pragma unroll
        for (int i = 0; i < 16; ++i) {
            float4 v = r4[i];
            s += v.x * v.x + v.y * v.y + v.z * v.z + v.w * v.w;
        }
        g_se[gid] = s;
    }
    if (gid == 0) g_sumsq = 0.0;
}

// ---- vq: 128 points x 1024 codes per block, 8x8 thread tile, cp.async pipelined,
//      fused gather + NCHW output write + loss partial ----
// dyn smem layout (floats): xs[8192] | es0[8192] | es1[8192] | ses[256] | sxs[128]
// after mainloop, region [SM_ES0 ..) is reused as qs[128][68], SM_SES as sidx[128]
#define SM_XS   0
#define SM_ES0  8192
#define SM_ES1  16384
#define SM_SES  24576
#define SM_SXS  24832
#define SM_FLOATS 24960

__global__ void __launch_bounds__(256) vq_kernel(const float* __restrict__ x,
                                                 const float* __restrict__ emb,
                                                 float* __restrict__ out) {
    extern __shared__ float sm[];
    const uint32_t smb = smem_u32(sm);
    const int tid = threadIdx.x;
    const int tx = tid & 15;          // 16 code groups x 8 codes = 128 codes/chunk
    const int ty = tid >> 4;          // 16 point groups x 8 pts = 128 pts
    const int bb  = blockIdx.x >> 3;
    const int hw0 = (blockIdx.x & 7) << 7;
    const float* xb = x + ((size_t)bb << 16) + hw0;

    // prologue: full x tile + chunk0 in group 0; chunk1 in group 1
    {
#pragma unroll
        for (int q = 0; q < 8; ++q) {
            int l = (q * 256 + tid) * 4;               // float offset in [64][128]
            cpa16(smb + (SM_XS + l) * 4, xb + (l >> 7) * HW + (l & 127));
        }
#pragma unroll
        for (int q = 0; q < 8; ++q) {
            int l = (q * 256 + tid) * 4;
            cpa16(smb + (SM_ES0 + l) * 4, g_et + (l >> 7) * KC + (l & 127));
        }
        if (tid < 32) cpa16(smb + (SM_SES + tid * 4) * 4, g_se + tid * 4);
        cpa_commit();
#pragma unroll
        for (int q = 0; q < 8; ++q) {
            int l = (q * 256 + tid) * 4;
            cpa16(smb + (SM_ES1 + l) * 4, g_et + (l >> 7) * KC + 128 + (l & 127));
        }
        if (tid < 32) cpa16(smb + (SM_SES + 128 + tid * 4) * 4, g_se + 128 + tid * 4);
        cpa_commit();
    }
    cpa_wait1();
    __syncthreads();

    // ||x||^2 per point
    if (tid < 128) {
        float s = 0.f;
#pragma unroll
        for (int d = 0; d < 64; ++d) {
            float v = sm[SM_XS + d * 128 + tid];
            s = fmaf(v, v, s);
        }
        sm[SM_SXS + tid] = s;
    }
    __syncthreads();

    float sx[8];
#pragma unroll
    for (int p = 0; p < 8; ++p) sx[p] = sm[SM_SXS + (ty << 3) + p];

    float bd[8];
    int   bk[8];
#pragma unroll
    for (int p = 0; p < 8; ++p) { bd[p] = 3.4e38f; bk[p] = 0; }

    for (int kc = 0; kc < 8; ++kc) {
        const int buf = kc & 1;
        const float* eb = sm + (buf ? SM_ES1 : SM_ES0);
        const float* sesb = sm + SM_SES + buf * 128;

        unsigned long long acc[8][4];
#pragma unroll
        for (int p = 0; p < 8; ++p)
#pragma unroll
            for (int j = 0; j < 4; ++j) acc[p][j] = 0ULL;

#pragma unroll 8
        for (int d = 0; d < 64; ++d) {
            const float* xr = sm + SM_XS + d * 128 + (ty << 3);
            float4 xa = *(const float4*)xr;
            float4 xc = *(const float4*)(xr + 4);
            unsigned long long xp[8];
            xp[0] = pack2(xa.x); xp[1] = pack2(xa.y);
            xp[2] = pack2(xa.z); xp[3] = pack2(xa.w);
            xp[4] = pack2(xc.x); xp[5] = pack2(xc.y);
            xp[6] = pack2(xc.z); xp[7] = pack2(xc.w);
            const ulonglong2* er = (const ulonglong2*)(eb + d * 128 + (tx << 3));
            ulonglong2 e01 = er[0];
            ulonglong2 e23 = er[1];
#pragma unroll
            for (int p = 0; p < 8; ++p) {
                acc[p][0] = fma2(xp[p], e01.x, acc[p][0]);
                acc[p][1] = fma2(xp[p], e01.y, acc[p][1]);
                acc[p][2] = fma2(xp[p], e23.x, acc[p][2]);
                acc[p][3] = fma2(xp[p], e23.y, acc[p][3]);
            }
        }

        // epilogue: distance + running argmin.
        // fmaf(-2,dot,sx) == fsub(sx, fmul(2,dot)) exactly (2*dot is exact).
        const int cb = (kc << 7) + (tx << 3);
#pragma unroll
        for (int p = 0; p < 8; ++p) {
#pragma unroll
            for (int j = 0; j < 4; ++j) {
                float da, db;
                unpack2(acc[p][j], da, db);
                float sea = sesb[(tx << 3) + 2 * j];
                float seb = sesb[(tx << 3) + 2 * j + 1];
                float va = __fadd_rn(__fmaf_rn(-2.f, da, sx[p]), sea);
                if (va < bd[p]) { bd[p] = va; bk[p] = cb + 2 * j; }
                float vb = __fadd_rn(__fmaf_rn(-2.f, db, sx[p]), seb);
                if (vb < bd[p]) { bd[p] = vb; bk[p] = cb + 2 * j + 1; }
            }
        }

        __syncthreads();          // everyone done reading buf
        if (kc + 2 < 8) {
            const int c0 = (kc + 2) << 7;
#pragma unroll
            for (int q = 0; q < 8; ++q) {
                int l = (q * 256 + tid) * 4;
                cpa16(smb + ((buf ? SM_ES1 : SM_ES0) + l) * 4,
                      g_et + (l >> 7) * KC + c0 + (l & 127));
            }
            if (tid < 32) cpa16(smb + (SM_SES + buf * 128 + tid * 4) * 4, g_se + c0 + tid * 4);
        }
        cpa_commit();
        if (kc < 7) { cpa_wait1(); __syncthreads(); }
    }

    // reduce over the 16 code-group lanes (bits 0..3 of lane id)
#pragma unroll
    for (int off = 1; off < 16; off <<= 1) {
#pragma unroll
        for (int p = 0; p < 8; ++p) {
            float od = __shfl_xor_sync(0xffffffffu, bd[p], off);
            int   ok = __shfl_xor_sync(0xffffffffu, bk[p], off);
            if (od < bd[p] || (od == bd[p] && ok < bk[p])) { bd[p] = od; bk[p] = ok; }
        }
    }

    // publish per-point argmin to smem + histogram
    int* sidx = (int*)(sm + SM_SES);
    if (tx == 0) {
#pragma unroll
        for (int p = 0; p < 8; ++p) {
            sidx[(ty << 3) + p] = bk[p];
            atomicAdd(&g_hist[bk[p]], 1);
        }
    }
    __syncthreads();

    // ---- fused gather: emb rows -> qs[128][68] (coalesced loads) ----
    float* qs = sm + SM_ES0;
#pragma unroll
    for (int q = 0; q < 8; ++q) {
        int t2 = q * 256 + tid;
        int p  = t2 >> 4;           // 0..127
        int f4 = t2 & 15;           // 0..15 float4 within row
        float4 v = ((const float4*)(emb + (size_t)sidx[p] * NC))[f4];
        *(float4*)(qs + p * 68 + f4 * 4) = v;
    }
    __syncthreads();

    // ---- output write (NCHW, coalesced) + loss partial ----
    const int lane = tid & 31, w = tid >> 5;
    float s = 0.f;
#pragma unroll
    for (int j = 0; j < 8; ++j) {
        int c = w * 8 + j;
        float* ob = out + (((size_t)bb << 6) + c) * HW + hw0;
#pragma unroll
        for (int g = 0; g < 4; ++g) {
            int p = g * 32 + lane;
            float qv = qs[p * 68 + c];
            float xv = sm[SM_XS + c * 128 + p];
            ob[p] = qv;
            float d = qv - xv;
            s = fmaf(d, d, s);
        }
    }
#pragma unroll
    for (int off = 16; off; off >>= 1) s += __shfl_xor_sync(0xffffffffu, s, off);
    float* red = sm + SM_SXS;       // reuse (sxs dead)
    if (lane == 0) red[w] = s;
    __syncthreads();
    if (tid == 0) {
        float t = 0.f;
#pragma unroll
        for (int i = 0; i < 8; ++i) t += red[i];
        atomicAdd(&g_sumsq, (double)t);
    }
}

// ---- loss + perplexity ----
__global__ void __launch_bounds__(1024) final_kernel(float* __restrict__ out, int nq) {
    __shared__ float red[32];
    int t = threadIdx.x;
    float p = (float)g_hist[t] * (1.0f / 65536.0f);
    float term = p * logf(p + 1e-10f);
#pragma unroll
    for (int off = 16; off; off >>= 1) term += __shfl_xor_sync(0xffffffffu, term, off);
    if ((t & 31) == 0) red[t >> 5] = term;
    __syncthreads();
    if (t < 32) {
        float v = red[t];
#pragma unroll
        for (int off = 16; off; off >>= 1) v += __shfl_xor_sync(0xffffffffu, v, off);
        if (t == 0) {
            float m = (float)(g_sumsq * (1.0 / (double)NELEM));
            out[nq]     = 1.25f * m;
            out[nq + 1] = expf(-v);
        }
    }
}

extern "C" void kernel_launch(void* const* d_in, const int* in_sizes, int n_in,
                              void* d_out, int out_size) {
    const float* x   = (const float*)d_in[0];
    const float* emb = (const float*)d_in[1];
    if (n_in >= 2 && in_sizes[0] == KC * NC && in_sizes[1] == NELEM) {
        const float* tmp = x; x = emb; emb = tmp;
    }
    float* out = (float*)d_out;
    int nq = out_size - 2;

    cudaFuncSetAttribute(vq_kernel, cudaFuncAttributeMaxDynamicSharedMemorySize,
                         SM_FLOATS * 4);

    prep_kernel<<<64, 256>>>(emb);
    vq_kernel<<<512, 256, SM_FLOATS * 4>>>(x, emb, out);
    final_kernel<<<1, 1024>>>(out, nq);
}

// round 5
// speedup vs baseline: 2.9907x; 1.0229x over previous
#include <cuda_runtime.h>
#include <math.h>
#include <stdint.h>

#define NB   64
#define NC   64
#define HW   1024
#define NPTS 65536
#define KC   1024
#define NELEM 4194304

__device__ float  g_et[NC * KC];     // transposed embeddings [d][c]
__device__ float  g_se[KC];
__device__ int    g_hist[KC];
__device__ double g_sumsq;

// ---- packed fp32x2 helpers ----
__device__ __forceinline__ unsigned long long fma2(unsigned long long a,
                                                   unsigned long long b,
                                                   unsigned long long c) {
    unsigned long long r;
    asm("fma.rn.f32x2 %0, %1, %2, %3;" : "=l"(r) : "l"(a), "l"(b), "l"(c));
    return r;
}
__device__ __forceinline__ unsigned long long add2(unsigned long long a,
                                                   unsigned long long b) {
    unsigned long long r;
    asm("add.rn.f32x2 %0, %1, %2;" : "=l"(r) : "l"(a), "l"(b));
    return r;
}
__device__ __forceinline__ unsigned long long pack2(float x) {
    unsigned long long r;
    asm("mov.b64 %0, {%1, %1};" : "=l"(r) : "f"(x));
    return r;
}
__device__ __forceinline__ void unpack2(unsigned long long v, float& lo, float& hi) {
    asm("mov.b64 {%0, %1}, %2;" : "=f"(lo), "=f"(hi) : "l"(v));
}
__device__ __forceinline__ uint32_t smem_u32(const void* p) {
    uint32_t a;
    asm("{ .reg .u64 t; cvta.to.shared.u64 t, %1; cvt.u32.u64 %0, t; }" : "=r"(a) : "l"(p));
    return a;
}
__device__ __forceinline__ void cpa16(uint32_t dst, const float* src) {
    asm volatile("cp.async.cg.shared.global [%0], [%1], 16;" :: "r"(dst), "l"(src));
}
__device__ __forceinline__ void cpa_commit() { asm volatile("cp.async.commit_group;"); }
__device__ __forceinline__ void cpa_wait1()  { asm volatile("cp.async.wait_group 1;"); }

// ---- zero hist/sumsq + compute se ----
__global__ void __launch_bounds__(256) zero_se_kernel(const float* __restrict__ emb) {
    int gid = blockIdx.x * 256 + threadIdx.x;   // grid 4 -> 1024
    g_hist[gid] = 0;
    const float4* r4 = (const float4*)(emb + (size_t)gid * NC);
    float s = 0.f;
#pragma unroll
    for (int i = 0; i < 16; ++i) {
        float4 v = r4[i];
        s += v.x * v.x + v.y * v.y + v.z * v.z + v.w * v.w;
    }
    g_se[gid] = s;
    if (gid == 0) g_sumsq = 0.0;
}

// ---- transpose half of emb -> g_et (d in [doff, doff+32)) ----
__global__ void __launch_bounds__(256) transpose_kernel(const float* __restrict__ emb,
                                                        int doff) {
    __shared__ float t[32][33];
    int tid = threadIdx.x;
    int bc = blockIdx.x;           // code tile (32 tiles of 32 codes)
    int lx = tid & 31, ly = tid >> 5;
#pragma unroll
    for (int r = 0; r < 4; ++r) {
        int c = bc * 32 + ly + r * 8;
        t[ly + r * 8][lx] = emb[c * NC + doff + lx];
    }
    __syncthreads();
#pragma unroll
    for (int r = 0; r < 4; ++r) {
        int d = doff + ly + r * 8;
        g_et[d * KC + bc * 32 + lx] = t[lx][ly + r * 8];
    }
}

// ---- vq: 128 points x 1024 codes per block, 8x8 thread tile, cp.async pipelined,
//      fused gather + NCHW output write + loss partial ----
#define SM_XS   0
#define SM_ES0  8192
#define SM_ES1  16384
#define SM_SES  24576
#define SM_SXS  24832
#define SM_FLOATS 24960

__global__ void __launch_bounds__(256) vq_kernel(const float* __restrict__ x,
                                                 const float* __restrict__ emb,
                                                 float* __restrict__ out) {
    extern __shared__ float sm[];
    const uint32_t smb = smem_u32(sm);
    const int tid = threadIdx.x;
    const int tx = tid & 15;          // 16 code groups x 8 codes = 128 codes/chunk
    const int ty = tid >> 4;          // 16 point groups x 8 pts = 128 pts
    const int bb  = blockIdx.x >> 3;
    const int hw0 = (blockIdx.x & 7) << 7;
    const float* xb = x + ((size_t)bb << 16) + hw0;

    // prologue: full x tile + chunk0 in group 0; chunk1 in group 1
    {
#pragma unroll
        for (int q = 0; q < 8; ++q) {
            int l = (q * 256 + tid) * 4;               // float offset in [64][128]
            cpa16(smb + (SM_XS + l) * 4, xb + (l >> 7) * HW + (l & 127));
        }
#pragma unroll
        for (int q = 0; q < 8; ++q) {
            int l = (q * 256 + tid) * 4;
            cpa16(smb + (SM_ES0 + l) * 4, g_et + (l >> 7) * KC + (l & 127));
        }
        if (tid < 32) cpa16(smb + (SM_SES + tid * 4) * 4, g_se + tid * 4);
        cpa_commit();
#pragma unroll
        for (int q = 0; q < 8; ++q) {
            int l = (q * 256 + tid) * 4;
            cpa16(smb + (SM_ES1 + l) * 4, g_et + (l >> 7) * KC + 128 + (l & 127));
        }
        if (tid < 32) cpa16(smb + (SM_SES + 128 + tid * 4) * 4, g_se + 128 + tid * 4);
        cpa_commit();
    }
    cpa_wait1();
    __syncthreads();

    // ||x||^2 per point
    if (tid < 128) {
        float s = 0.f;
#pragma unroll
        for (int d = 0; d < 64; ++d) {
            float v = sm[SM_XS + d * 128 + tid];
            s = fmaf(v, v, s);
        }
        sm[SM_SXS + tid] = s;
    }
    __syncthreads();

    float sx[8];
#pragma unroll
    for (int p = 0; p < 8; ++p) sx[p] = sm[SM_SXS + (ty << 3) + p];
    const unsigned long long NEG2 = pack2(-2.0f);

    float bd[8];
    int   bk[8];
#pragma unroll
    for (int p = 0; p < 8; ++p) { bd[p] = 3.4e38f; bk[p] = 0; }

    for (int kc = 0; kc < 8; ++kc) {
        const int buf = kc & 1;
        const float* eb = sm + (buf ? SM_ES1 : SM_ES0);
        const float* sesb = sm + SM_SES + buf * 128;

        unsigned long long acc[8][4];
#pragma unroll
        for (int p = 0; p < 8; ++p)
#pragma unroll
            for (int j = 0; j < 4; ++j) acc[p][j] = 0ULL;

#pragma unroll 8
        for (int d = 0; d < 64; ++d) {
            const float* xr = sm + SM_XS + d * 128 + (ty << 3);
            float4 xa = *(const float4*)xr;
            float4 xc = *(const float4*)(xr + 4);
            unsigned long long xp[8];
            xp[0] = pack2(xa.x); xp[1] = pack2(xa.y);
            xp[2] = pack2(xa.z); xp[3] = pack2(xa.w);
            xp[4] = pack2(xc.x); xp[5] = pack2(xc.y);
            xp[6] = pack2(xc.z); xp[7] = pack2(xc.w);
            const ulonglong2* er = (const ulonglong2*)(eb + d * 128 + (tx << 3));
            ulonglong2 e01 = er[0];
            ulonglong2 e23 = er[1];
#pragma unroll
            for (int p = 0; p < 8; ++p) {
                acc[p][0] = fma2(xp[p], e01.x, acc[p][0]);
                acc[p][1] = fma2(xp[p], e01.y, acc[p][1]);
                acc[p][2] = fma2(xp[p], e23.x, acc[p][2]);
                acc[p][3] = fma2(xp[p], e23.y, acc[p][3]);
            }
        }

        // packed epilogue: v = (-2*dot + sx) + se per lane (bit-exact vs scalar)
        const ulonglong2* ses2 = (const ulonglong2*)(sesb + (tx << 3));
        ulonglong2 seA = ses2[0];   // se pairs: codes (0,1),(2,3)
        ulonglong2 seB = ses2[1];   // codes (4,5),(6,7)
        const int cb = (kc << 7) + (tx << 3);
#pragma unroll
        for (int p = 0; p < 8; ++p) {
            unsigned long long sxp = pack2(sx[p]);
            unsigned long long v0 = add2(fma2(NEG2, acc[p][0], sxp), seA.x);
            unsigned long long v1 = add2(fma2(NEG2, acc[p][1], sxp), seA.y);
            unsigned long long v2 = add2(fma2(NEG2, acc[p][2], sxp), seB.x);
            unsigned long long v3 = add2(fma2(NEG2, acc[p][3], sxp), seB.y);
            float a, b;
            unpack2(v0, a, b);
            if (a < bd[p]) { bd[p] = a; bk[p] = cb; }
            if (b < bd[p]) { bd[p] = b; bk[p] = cb + 1; }
            unpack2(v1, a, b);
            if (a < bd[p]) { bd[p] = a; bk[p] = cb + 2; }
            if (b < bd[p]) { bd[p] = b; bk[p] = cb + 3; }
            unpack2(v2, a, b);
            if (a < bd[p]) { bd[p] = a; bk[p] = cb + 4; }
            if (b < bd[p]) { bd[p] = b; bk[p] = cb + 5; }
            unpack2(v3, a, b);
            if (a < bd[p]) { bd[p] = a; bk[p] = cb + 6; }
            if (b < bd[p]) { bd[p] = b; bk[p] = cb + 7; }
        }

        __syncthreads();          // everyone done reading buf
        if (kc + 2 < 8) {
            const int c0 = (kc + 2) << 7;
#pragma unroll
            for (int q = 0; q < 8; ++q) {
                int l = (q * 256 + tid) * 4;
                cpa16(smb + ((buf ? SM_ES1 : SM_ES0) + l) * 4,
                      g_et + (l >> 7) * KC + c0 + (l & 127));
            }
            if (tid < 32) cpa16(smb + (SM_SES + buf * 128 + tid * 4) * 4, g_se + c0 + tid * 4);
        }
        cpa_commit();
        if (kc < 7) { cpa_wait1(); __syncthreads(); }
    }

    // reduce over the 16 code-group lanes (bits 0..3 of lane id)
#pragma unroll
    for (int off = 1; off < 16; off <<= 1) {
#pragma unroll
        for (int p = 0; p < 8; ++p) {
            float od = __shfl_xor_sync(0xffffffffu, bd[p], off);
            int   ok = __shfl_xor_sync(0xffffffffu, bk[p], off);
            if (od < bd[p] || (od == bd[p] && ok < bk[p])) { bd[p] = od; bk[p] = ok; }
        }
    }

    // publish per-point argmin to smem + histogram
    int* sidx = (int*)(sm + SM_SES);
    if (tx == 0) {
#pragma unroll
        for (int p = 0; p < 8; ++p) {
            sidx[(ty << 3) + p] = bk[p];
            atomicAdd(&g_hist[bk[p]], 1);
        }
    }
    __syncthreads();

    // ---- fused gather: emb rows -> qs[128][68] (coalesced loads) ----
    float* qs = sm + SM_ES0;
#pragma unroll
    for (int q = 0; q < 8; ++q) {
        int t2 = q * 256 + tid;
        int p  = t2 >> 4;           // 0..127
        int f4 = t2 & 15;           // 0..15 float4 within row
        float4 v = ((const float4*)(emb + (size_t)sidx[p] * NC))[f4];
        *(float4*)(qs + p * 68 + f4 * 4) = v;
    }
    __syncthreads();

    // ---- output write (NCHW, coalesced) + loss partial ----
    const int lane = tid & 31, w = tid >> 5;
    float s = 0.f;
#pragma unroll
    for (int j = 0; j < 8; ++j) {
        int c = w * 8 + j;
        float* ob = out + (((size_t)bb << 6) + c) * HW + hw0;
#pragma unroll
        for (int g = 0; g < 4; ++g) {
            int p = g * 32 + lane;
            float qv = qs[p * 68 + c];
            float xv = sm[SM_XS + c * 128 + p];
            ob[p] = qv;
            float d = qv - xv;
            s = fmaf(d, d, s);
        }
    }
#pragma unroll
    for (int off = 16; off; off >>= 1) s += __shfl_xor_sync(0xffffffffu, s, off);
    float* red = sm + SM_SXS;       // reuse (sxs dead)
    if (lane == 0) red[w] = s;
    __syncthreads();
    if (tid == 0) {
        float t = 0.f;
#pragma unroll
        for (int i = 0; i < 8; ++i) t += red[i];
        atomicAdd(&g_sumsq, (double)t);
    }
}

// ---- loss + perplexity ----
__global__ void __launch_bounds__(1024) final_kernel(float* __restrict__ out, int nq) {
    __shared__ float red[32];
    int t = threadIdx.x;
    float p = (float)g_hist[t] * (1.0f / 65536.0f);
    float term = p * logf(p + 1e-10f);
#pragma unroll
    for (int off = 16; off; off >>= 1) term += __shfl_xor_sync(0xffffffffu, term, off);
    if ((t & 31) == 0) red[t >> 5] = term;
    __syncthreads();
    if (t < 32) {
        float v = red[t];
#pragma unroll
        for (int off = 16; off; off >>= 1) v += __shfl_xor_sync(0xffffffffu, v, off);
        if (t == 0) {
            float m = (float)(g_sumsq * (1.0 / (double)NELEM));
            out[nq]     = 1.25f * m;
            out[nq + 1] = expf(-v);
        }
    }
}

extern "C" void kernel_launch(void* const* d_in, const int* in_sizes, int n_in,
                              void* d_out, int out_size) {
    const float* x   = (const float*)d_in[0];
    const float* emb = (const float*)d_in[1];
    if (n_in >= 2 && in_sizes[0] == KC * NC && in_sizes[1] == NELEM) {
        const float* tmp = x; x = emb; emb = tmp;
    }
    float* out = (float*)d_out;
    int nq = out_size - 2;

    cudaFuncSetAttribute(vq_kernel, cudaFuncAttributeMaxDynamicSharedMemorySize,
                         SM_FLOATS * 4);

    // ordering: vq is the 4th launch -> ncu (-s/-c bounded) captures it
    zero_se_kernel<<<4, 256>>>(emb);
    transpose_kernel<<<32, 256>>>(emb, 0);
    transpose_kernel<<<32, 256>>>(emb, 32);
    vq_kernel<<<512, 256, SM_FLOATS * 4>>>(x, emb, out);
    final_kernel<<<1, 1024>>>(out, nq);
}

// round 6
// speedup vs baseline: 3.1096x; 1.0397x over previous
#include <cuda_runtime.h>
#include <math.h>
#include <stdint.h>

#define NB   64
#define NC   64
#define HW   1024
#define NPTS 65536
#define KC   1024
#define NELEM 4194304

__device__ float  g_et[NC * KC];     // transposed embeddings [d][c]
__device__ float  g_se[KC];
__device__ int    g_hist[KC];
__device__ double g_sumsq;

// ---- packed fp32x2 helpers ----
__device__ __forceinline__ unsigned long long fma2(unsigned long long a,
                                                   unsigned long long b,
                                                   unsigned long long c) {
    unsigned long long r;
    asm("fma.rn.f32x2 %0, %1, %2, %3;" : "=l"(r) : "l"(a), "l"(b), "l"(c));
    return r;
}
__device__ __forceinline__ unsigned long long add2(unsigned long long a,
                                                   unsigned long long b) {
    unsigned long long r;
    asm("add.rn.f32x2 %0, %1, %2;" : "=l"(r) : "l"(a), "l"(b));
    return r;
}
__device__ __forceinline__ unsigned long long pack2(float x) {
    unsigned long long r;
    asm("mov.b64 %0, {%1, %1};" : "=l"(r) : "f"(x));
    return r;
}
__device__ __forceinline__ void unpack2(unsigned long long v, float& lo, float& hi) {
    asm("mov.b64 {%0, %1}, %2;" : "=f"(lo), "=f"(hi) : "l"(v));
}
__device__ __forceinline__ uint32_t smem_u32(const void* p) {
    uint32_t a;
    asm("{ .reg .u64 t; cvta.to.shared.u64 t, %1; cvt.u32.u64 %0, t; }" : "=r"(a) : "l"(p));
    return a;
}
__device__ __forceinline__ void cpa16(uint32_t dst, const float* src) {
    asm volatile("cp.async.cg.shared.global [%0], [%1], 16;" :: "r"(dst), "l"(src));
}
__device__ __forceinline__ void cpa_commit() { asm volatile("cp.async.commit_group;"); }
__device__ __forceinline__ void cpa_wait1()  { asm volatile("cp.async.wait_group 1;"); }

// ---- zero hist/sumsq + compute se ----
__global__ void __launch_bounds__(256) zero_se_kernel(const float* __restrict__ emb) {
    int gid = blockIdx.x * 256 + threadIdx.x;   // grid 4 -> 1024
    g_hist[gid] = 0;
    const float4* r4 = (const float4*)(emb + (size_t)gid * NC);
    float s = 0.f;
#pragma unroll
    for (int i = 0; i < 16; ++i) {
        float4 v = r4[i];
        s += v.x * v.x + v.y * v.y + v.z * v.z + v.w * v.w;
    }
    g_se[gid] = s;
    if (gid == 0) g_sumsq = 0.0;
}

// ---- transpose half of emb -> g_et (d in [doff, doff+32)) ----
__global__ void __launch_bounds__(256) transpose_kernel(const float* __restrict__ emb,
                                                        int doff) {
    __shared__ float t[32][33];
    int tid = threadIdx.x;
    int bc = blockIdx.x;           // code tile (32 tiles of 32 codes)
    int lx = tid & 31, ly = tid >> 5;
#pragma unroll
    for (int r = 0; r < 4; ++r) {
        int c = bc * 32 + ly + r * 8;
        t[ly + r * 8][lx] = emb[c * NC + doff + lx];
    }
    __syncthreads();
#pragma unroll
    for (int r = 0; r < 4; ++r) {
        int d = doff + ly + r * 8;
        g_et[d * KC + bc * 32 + lx] = t[lx][ly + r * 8];
    }
}

// ---- vq: 128 points x 1024 codes per block, 8x8 thread tile, cp.async pipelined,
//      fused gather + NCHW output write + loss partial ----
// code->thread map per 128-chunk: thread tx owns codes {4tx..4tx+3, 64+4tx..64+4tx+3}
// so the two e LDS.128 reads hit granules tx and 16+tx (bank-conflict-free phases).
#define SM_XS   0
#define SM_ES0  8192
#define SM_ES1  16384
#define SM_SES  24576
#define SM_SXS  24832
#define SM_FLOATS 24960

__global__ void __launch_bounds__(256) vq_kernel(const float* __restrict__ x,
                                                 const float* __restrict__ emb,
                                                 float* __restrict__ out) {
    extern __shared__ float sm[];
    const uint32_t smb = smem_u32(sm);
    const int tid = threadIdx.x;
    const int tx = tid & 15;          // 16 code groups
    const int ty = tid >> 4;          // 16 point groups x 8 pts = 128 pts
    const int bb  = blockIdx.x >> 3;
    const int hw0 = (blockIdx.x & 7) << 7;
    const float* xb = x + ((size_t)bb << 16) + hw0;

    // prologue: full x tile + chunk0 in group 0; chunk1 in group 1
    {
#pragma unroll
        for (int q = 0; q < 8; ++q) {
            int l = (q * 256 + tid) * 4;               // float offset in [64][128]
            cpa16(smb + (SM_XS + l) * 4, xb + (l >> 7) * HW + (l & 127));
        }
#pragma unroll
        for (int q = 0; q < 8; ++q) {
            int l = (q * 256 + tid) * 4;
            cpa16(smb + (SM_ES0 + l) * 4, g_et + (l >> 7) * KC + (l & 127));
        }
        if (tid < 32) cpa16(smb + (SM_SES + tid * 4) * 4, g_se + tid * 4);
        cpa_commit();
#pragma unroll
        for (int q = 0; q < 8; ++q) {
            int l = (q * 256 + tid) * 4;
            cpa16(smb + (SM_ES1 + l) * 4, g_et + (l >> 7) * KC + 128 + (l & 127));
        }
        if (tid < 32) cpa16(smb + (SM_SES + 128 + tid * 4) * 4, g_se + 128 + tid * 4);
        cpa_commit();
    }
    cpa_wait1();
    __syncthreads();

    // ||x||^2 per point
    if (tid < 128) {
        float s = 0.f;
#pragma unroll
        for (int d = 0; d < 64; ++d) {
            float v = sm[SM_XS + d * 128 + tid];
            s = fmaf(v, v, s);
        }
        sm[SM_SXS + tid] = s;
    }
    __syncthreads();

    float sx[8];
#pragma unroll
    for (int p = 0; p < 8; ++p) sx[p] = sm[SM_SXS + (ty << 3) + p];
    const unsigned long long NEG2 = pack2(-2.0f);

    float bd[8];
    int   bk[8];
#pragma unroll
    for (int p = 0; p < 8; ++p) { bd[p] = 3.4e38f; bk[p] = 0; }

    for (int kc = 0; kc < 8; ++kc) {
        const int buf = kc & 1;
        const float* eb = sm + (buf ? SM_ES1 : SM_ES0);
        const float* sesb = sm + SM_SES + buf * 128;

        unsigned long long acc[8][4];
#pragma unroll
        for (int p = 0; p < 8; ++p)
#pragma unroll
            for (int j = 0; j < 4; ++j) acc[p][j] = 0ULL;

#pragma unroll 8
        for (int d = 0; d < 64; ++d) {
            const float* xr = sm + SM_XS + d * 128 + (ty << 3);
            float4 xa = *(const float4*)xr;
            float4 xc = *(const float4*)(xr + 4);
            unsigned long long xp[8];
            xp[0] = pack2(xa.x); xp[1] = pack2(xa.y);
            xp[2] = pack2(xa.z); xp[3] = pack2(xa.w);
            xp[4] = pack2(xc.x); xp[5] = pack2(xc.y);
            xp[6] = pack2(xc.z); xp[7] = pack2(xc.w);
            // conflict-free granule reads: codes 4tx..4tx+3 and 64+4tx..64+4tx+3
            ulonglong2 e01 = *(const ulonglong2*)(eb + d * 128 + (tx << 2));
            ulonglong2 e23 = *(const ulonglong2*)(eb + d * 128 + 64 + (tx << 2));
#pragma unroll
            for (int p = 0; p < 8; ++p) {
                acc[p][0] = fma2(xp[p], e01.x, acc[p][0]);
                acc[p][1] = fma2(xp[p], e01.y, acc[p][1]);
                acc[p][2] = fma2(xp[p], e23.x, acc[p][2]);
                acc[p][3] = fma2(xp[p], e23.y, acc[p][3]);
            }
        }

        // packed epilogue: v = (-2*dot + sx) + se per lane (bit-exact vs scalar)
        ulonglong2 seA = *(const ulonglong2*)(sesb + (tx << 2));        // codes 4tx..4tx+3
        ulonglong2 seB = *(const ulonglong2*)(sesb + 64 + (tx << 2));   // codes 64+4tx..
        const int cb = (kc << 7) + (tx << 2);
#pragma unroll
        for (int p = 0; p < 8; ++p) {
            unsigned long long sxp = pack2(sx[p]);
            unsigned long long v0 = add2(fma2(NEG2, acc[p][0], sxp), seA.x);
            unsigned long long v1 = add2(fma2(NEG2, acc[p][1], sxp), seA.y);
            unsigned long long v2 = add2(fma2(NEG2, acc[p][2], sxp), seB.x);
            unsigned long long v3 = add2(fma2(NEG2, acc[p][3], sxp), seB.y);
            float a, b;
            unpack2(v0, a, b);
            if (a < bd[p]) { bd[p] = a; bk[p] = cb; }
            if (b < bd[p]) { bd[p] = b; bk[p] = cb + 1; }
            unpack2(v1, a, b);
            if (a < bd[p]) { bd[p] = a; bk[p] = cb + 2; }
            if (b < bd[p]) { bd[p] = b; bk[p] = cb + 3; }
            unpack2(v2, a, b);
            if (a < bd[p]) { bd[p] = a; bk[p] = cb + 64; }
            if (b < bd[p]) { bd[p] = b; bk[p] = cb + 65; }
            unpack2(v3, a, b);
            if (a < bd[p]) { bd[p] = a; bk[p] = cb + 66; }
            if (b < bd[p]) { bd[p] = b; bk[p] = cb + 67; }
        }

        __syncthreads();          // everyone done reading buf
        if (kc + 2 < 8) {
            const int c0 = (kc + 2) << 7;
#pragma unroll
            for (int q = 0; q < 8; ++q) {
                int l = (q * 256 + tid) * 4;
                cpa16(smb + ((buf ? SM_ES1 : SM_ES0) + l) * 4,
                      g_et + (l >> 7) * KC + c0 + (l & 127));
            }
            if (tid < 32) cpa16(smb + (SM_SES + buf * 128 + tid * 4) * 4, g_se + c0 + tid * 4);
        }
        cpa_commit();
        if (kc < 7) { cpa_wait1(); __syncthreads(); }
    }

    // reduce over the 16 code-group lanes (bits 0..3 of lane id)
#pragma unroll
    for (int off = 1; off < 16; off <<= 1) {
#pragma unroll
        for (int p = 0; p < 8; ++p) {
            float od = __shfl_xor_sync(0xffffffffu, bd[p], off);
            int   ok = __shfl_xor_sync(0xffffffffu, bk[p], off);
            if (od < bd[p] || (od == bd[p] && ok < bk[p])) { bd[p] = od; bk[p] = ok; }
        }
    }

    // publish per-point argmin to smem + histogram
    int* sidx = (int*)(sm + SM_SES);
    if (tx == 0) {
#pragma unroll
        for (int p = 0; p < 8; ++p) {
            sidx[(ty << 3) + p] = bk[p];
            atomicAdd(&g_hist[bk[p]], 1);
        }
    }
    __syncthreads();

    // ---- fused gather: emb rows -> qs[128][68] (coalesced loads) ----
    float* qs = sm + SM_ES0;
#pragma unroll
    for (int q = 0; q < 8; ++q) {
        int t2 = q * 256 + tid;
        int p  = t2 >> 4;           // 0..127
        int f4 = t2 & 15;           // 0..15 float4 within row
        float4 v = ((const float4*)(emb + (size_t)sidx[p] * NC))[f4];
        *(float4*)(qs + p * 68 + f4 * 4) = v;
    }
    __syncthreads();

    // ---- output write (NCHW, coalesced) + loss partial ----
    const int lane = tid & 31, w = tid >> 5;
    float s = 0.f;
#pragma unroll
    for (int j = 0; j < 8; ++j) {
        int c = w * 8 + j;
        float* ob = out + (((size_t)bb << 6) + c) * HW + hw0;
#pragma unroll
        for (int g = 0; g < 4; ++g) {
            int p = g * 32 + lane;
            float qv = qs[p * 68 + c];
            float xv = sm[SM_XS + c * 128 + p];
            ob[p] = qv;
            float d = qv - xv;
            s = fmaf(d, d, s);
        }
    }
#pragma unroll
    for (int off = 16; off; off >>= 1) s += __shfl_xor_sync(0xffffffffu, s, off);
    float* red = sm + SM_SXS;       // reuse (sxs dead)
    if (lane == 0) red[w] = s;
    __syncthreads();
    if (tid == 0) {
        float t = 0.f;
#pragma unroll
        for (int i = 0; i < 8; ++i) t += red[i];
        atomicAdd(&g_sumsq, (double)t);
    }
}

// ---- loss + perplexity ----
__global__ void __launch_bounds__(1024) final_kernel(float* __restrict__ out, int nq) {
    __shared__ float red[32];
    int t = threadIdx.x;
    float p = (float)g_hist[t] * (1.0f / 65536.0f);
    float term = p * logf(p + 1e-10f);
#pragma unroll
    for (int off = 16; off; off >>= 1) term += __shfl_xor_sync(0xffffffffu, term, off);
    if ((t & 31) == 0) red[t >> 5] = term;
    __syncthreads();
    if (t < 32) {
        float v = red[t];
#pragma unroll
        for (int off = 16; off; off >>= 1) v += __shfl_xor_sync(0xffffffffu, v, off);
        if (t == 0) {
            float m = (float)(g_sumsq * (1.0 / (double)NELEM));
            out[nq]     = 1.25f * m;
            out[nq + 1] = expf(-v);
        }
    }
}

extern "C" void kernel_launch(void* const* d_in, const int* in_sizes, int n_in,
                              void* d_out, int out_size) {
    const float* x   = (const float*)d_in[0];
    const float* emb = (const float*)d_in[1];
    if (n_in >= 2 && in_sizes[0] == KC * NC && in_sizes[1] == NELEM) {
        const float* tmp = x; x = emb; emb = tmp;
    }
    float* out = (float*)d_out;
    int nq = out_size - 2;

    cudaFuncSetAttribute(vq_kernel, cudaFuncAttributeMaxDynamicSharedMemorySize,
                         SM_FLOATS * 4);

    // ordering: vq is the 4th launch -> ncu (-s/-c bounded) captures it
    zero_se_kernel<<<4, 256>>>(emb);
    transpose_kernel<<<32, 256>>>(emb, 0);
    transpose_kernel<<<32, 256>>>(emb, 32);
    vq_kernel<<<512, 256, SM_FLOATS * 4>>>(x, emb, out);
    final_kernel<<<1, 1024>>>(out, nq);
}

// round 7
// speedup vs baseline: 3.1138x; 1.0014x over previous
#include <cuda_runtime.h>
#include <math.h>
#include <stdint.h>

#define NB   64
#define NC   64
#define HW   1024
#define NPTS 65536
#define KC   1024
#define NELEM 4194304

__device__ float  g_et[NC * KC];     // transposed embeddings [d][c]
__device__ float  g_se[KC];
__device__ int    g_hist[KC];
__device__ double g_sumsq;

// ---- packed fp32x2 helpers ----
__device__ __forceinline__ unsigned long long fma2(unsigned long long a,
                                                   unsigned long long b,
                                                   unsigned long long c) {
    unsigned long long r;
    asm("fma.rn.f32x2 %0, %1, %2, %3;" : "=l"(r) : "l"(a), "l"(b), "l"(c));
    return r;
}
__device__ __forceinline__ unsigned long long add2(unsigned long long a,
                                                   unsigned long long b) {
    unsigned long long r;
    asm("add.rn.f32x2 %0, %1, %2;" : "=l"(r) : "l"(a), "l"(b));
    return r;
}
__device__ __forceinline__ unsigned long long pack2(float x) {
    unsigned long long r;
    asm("mov.b64 %0, {%1, %1};" : "=l"(r) : "f"(x));
    return r;
}
__device__ __forceinline__ void unpack2(unsigned long long v, float& lo, float& hi) {
    asm("mov.b64 {%0, %1}, %2;" : "=f"(lo), "=f"(hi) : "l"(v));
}
__device__ __forceinline__ uint32_t smem_u32(const void* p) {
    uint32_t a;
    asm("{ .reg .u64 t; cvta.to.shared.u64 t, %1; cvt.u32.u64 %0, t; }" : "=r"(a) : "l"(p));
    return a;
}
__device__ __forceinline__ void cpa16(uint32_t dst, const float* src) {
    asm volatile("cp.async.cg.shared.global [%0], [%1], 16;" :: "r"(dst), "l"(src));
}
__device__ __forceinline__ void cpa_commit() { asm volatile("cp.async.commit_group;"); }
__device__ __forceinline__ void cpa_wait1()  { asm volatile("cp.async.wait_group 1;"); }

// ---- zero hist/sumsq + compute se ----
__global__ void __launch_bounds__(256) zero_se_kernel(const float* __restrict__ emb) {
    int gid = blockIdx.x * 256 + threadIdx.x;   // grid 4 -> 1024
    g_hist[gid] = 0;
    const float4* r4 = (const float4*)(emb + (size_t)gid * NC);
    float s = 0.f;
#pragma unroll
    for (int i = 0; i < 16; ++i) {
        float4 v = r4[i];
        s += v.x * v.x + v.y * v.y + v.z * v.z + v.w * v.w;
    }
    g_se[gid] = s;
    if (gid == 0) g_sumsq = 0.0;
}

// ---- transpose half of emb -> g_et (d in [doff, doff+32)) ----
__global__ void __launch_bounds__(256) transpose_kernel(const float* __restrict__ emb,
                                                        int doff) {
    __shared__ float t[32][33];
    int tid = threadIdx.x;
    int bc = blockIdx.x;           // code tile (32 tiles of 32 codes)
    int lx = tid & 31, ly = tid >> 5;
#pragma unroll
    for (int r = 0; r < 4; ++r) {
        int c = bc * 32 + ly + r * 8;
        t[ly + r * 8][lx] = emb[c * NC + doff + lx];
    }
    __syncthreads();
#pragma unroll
    for (int r = 0; r < 4; ++r) {
        int d = doff + ly + r * 8;
        g_et[d * KC + bc * 32 + lx] = t[lx][ly + r * 8];
    }
}

// ---- vq: 128 points x 1024 codes per block, 8x8 thread tile, cp.async pipelined,
//      fused gather + NCHW output write + loss partial ----
// code->thread map per 128-chunk: thread tx owns codes {4tx..4tx+3, 64+4tx..64+4tx+3}
// so the two e LDS.128 reads hit granules tx and 16+tx (bank-conflict-free phases).
#define SM_XS   0
#define SM_ES0  8192
#define SM_ES1  16384
#define SM_SES  24576
#define SM_SXS  24832
#define SM_FLOATS 24960

__global__ void __launch_bounds__(256) vq_kernel(const float* __restrict__ x,
                                                 const float* __restrict__ emb,
                                                 float* __restrict__ out) {
    extern __shared__ float sm[];
    const uint32_t smb = smem_u32(sm);
    const int tid = threadIdx.x;
    const int tx = tid & 15;          // 16 code groups
    const int ty = tid >> 4;          // 16 point groups x 8 pts = 128 pts
    const int bb  = blockIdx.x >> 3;
    const int hw0 = (blockIdx.x & 7) << 7;
    const float* xb = x + ((size_t)bb << 16) + hw0;

    // prologue: full x tile + chunk0 in group 0; chunk1 in group 1
    {
#pragma unroll
        for (int q = 0; q < 8; ++q) {
            int l = (q * 256 + tid) * 4;               // float offset in [64][128]
            cpa16(smb + (SM_XS + l) * 4, xb + (l >> 7) * HW + (l & 127));
        }
#pragma unroll
        for (int q = 0; q < 8; ++q) {
            int l = (q * 256 + tid) * 4;
            cpa16(smb + (SM_ES0 + l) * 4, g_et + (l >> 7) * KC + (l & 127));
        }
        if (tid < 32) cpa16(smb + (SM_SES + tid * 4) * 4, g_se + tid * 4);
        cpa_commit();
#pragma unroll
        for (int q = 0; q < 8; ++q) {
            int l = (q * 256 + tid) * 4;
            cpa16(smb + (SM_ES1 + l) * 4, g_et + (l >> 7) * KC + 128 + (l & 127));
        }
        if (tid < 32) cpa16(smb + (SM_SES + 128 + tid * 4) * 4, g_se + 128 + tid * 4);
        cpa_commit();
    }
    cpa_wait1();
    __syncthreads();

    // ||x||^2 per point
    if (tid < 128) {
        float s = 0.f;
#pragma unroll
        for (int d = 0; d < 64; ++d) {
            float v = sm[SM_XS + d * 128 + tid];
            s = fmaf(v, v, s);
        }
        sm[SM_SXS + tid] = s;
    }
    __syncthreads();

    float sx[8];
#pragma unroll
    for (int p = 0; p < 8; ++p) sx[p] = sm[SM_SXS + (ty << 3) + p];
    const unsigned long long NEG2 = pack2(-2.0f);

    float bd[8];
    int   bk[8];
#pragma unroll
    for (int p = 0; p < 8; ++p) { bd[p] = 3.4e38f; bk[p] = 0; }

    for (int kc = 0; kc < 8; ++kc) {
        const int buf = kc & 1;
        const float* eb = sm + (buf ? SM_ES1 : SM_ES0);
        const float* sesb = sm + SM_SES + buf * 128;

        unsigned long long acc[8][4];
#pragma unroll
        for (int p = 0; p < 8; ++p)
#pragma unroll
            for (int j = 0; j < 4; ++j) acc[p][j] = 0ULL;

#pragma unroll 8
        for (int d = 0; d < 64; ++d) {
            const float* xr = sm + SM_XS + d * 128 + (ty << 3);
            float4 xa = *(const float4*)xr;
            float4 xc = *(const float4*)(xr + 4);
            unsigned long long xp[8];
            xp[0] = pack2(xa.x); xp[1] = pack2(xa.y);
            xp[2] = pack2(xa.z); xp[3] = pack2(xa.w);
            xp[4] = pack2(xc.x); xp[5] = pack2(xc.y);
            xp[6] = pack2(xc.z); xp[7] = pack2(xc.w);
            // conflict-free granule reads: codes 4tx..4tx+3 and 64+4tx..64+4tx+3
            ulonglong2 e01 = *(const ulonglong2*)(eb + d * 128 + (tx << 2));
            ulonglong2 e23 = *(const ulonglong2*)(eb + d * 128 + 64 + (tx << 2));
#pragma unroll
            for (int p = 0; p < 8; ++p) {
                acc[p][0] = fma2(xp[p], e01.x, acc[p][0]);
                acc[p][1] = fma2(xp[p], e01.y, acc[p][1]);
                acc[p][2] = fma2(xp[p], e23.x, acc[p][2]);
                acc[p][3] = fma2(xp[p], e23.y, acc[p][3]);
            }
        }

        // packed epilogue: v = (-2*dot + sx) + se per lane (bit-exact vs scalar)
        ulonglong2 seA = *(const ulonglong2*)(sesb + (tx << 2));        // codes 4tx..4tx+3
        ulonglong2 seB = *(const ulonglong2*)(sesb + 64 + (tx << 2));   // codes 64+4tx..
        const int cb = (kc << 7) + (tx << 2);
#pragma unroll
        for (int p = 0; p < 8; ++p) {
            unsigned long long sxp = pack2(sx[p]);
            unsigned long long v0 = add2(fma2(NEG2, acc[p][0], sxp), seA.x);
            unsigned long long v1 = add2(fma2(NEG2, acc[p][1], sxp), seA.y);
            unsigned long long v2 = add2(fma2(NEG2, acc[p][2], sxp), seB.x);
            unsigned long long v3 = add2(fma2(NEG2, acc[p][3], sxp), seB.y);
            float a, b;
            unpack2(v0, a, b);
            if (a < bd[p]) { bd[p] = a; bk[p] = cb; }
            if (b < bd[p]) { bd[p] = b; bk[p] = cb + 1; }
            unpack2(v1, a, b);
            if (a < bd[p]) { bd[p] = a; bk[p] = cb + 2; }
            if (b < bd[p]) { bd[p] = b; bk[p] = cb + 3; }
            unpack2(v2, a, b);
            if (a < bd[p]) { bd[p] = a; bk[p] = cb + 64; }
            if (b < bd[p]) { bd[p] = b; bk[p] = cb + 65; }
            unpack2(v3, a, b);
            if (a < bd[p]) { bd[p] = a; bk[p] = cb + 66; }
            if (b < bd[p]) { bd[p] = b; bk[p] = cb + 67; }
        }

        __syncthreads();          // everyone done reading buf
        if (kc + 2 < 8) {
            const int c0 = (kc + 2) << 7;
#pragma unroll
            for (int q = 0; q < 8; ++q) {
                int l = (q * 256 + tid) * 4;
                cpa16(smb + ((buf ? SM_ES1 : SM_ES0) + l) * 4,
                      g_et + (l >> 7) * KC + c0 + (l & 127));
            }
            if (tid < 32) cpa16(smb + (SM_SES + buf * 128 + tid * 4) * 4, g_se + c0 + tid * 4);
        }
        cpa_commit();
        if (kc < 7) { cpa_wait1(); __syncthreads(); }
    }

    // reduce over the 16 code-group lanes (bits 0..3 of lane id)
#pragma unroll
    for (int off = 1; off < 16; off <<= 1) {
#pragma unroll
        for (int p = 0; p < 8; ++p) {
            float od = __shfl_xor_sync(0xffffffffu, bd[p], off);
            int   ok = __shfl_xor_sync(0xffffffffu, bk[p], off);
            if (od < bd[p] || (od == bd[p] && ok < bk[p])) { bd[p] = od; bk[p] = ok; }
        }
    }

    // publish per-point argmin to smem + histogram
    int* sidx = (int*)(sm + SM_SES);
    if (tx == 0) {
#pragma unroll
        for (int p = 0; p < 8; ++p) {
            sidx[(ty << 3) + p] = bk[p];
            atomicAdd(&g_hist[bk[p]], 1);
        }
    }
    __syncthreads();

    // ---- fused gather: emb rows -> qs[128][68] (coalesced loads) ----
    float* qs = sm + SM_ES0;
#pragma unroll
    for (int q = 0; q < 8; ++q) {
        int t2 = q * 256 + tid;
        int p  = t2 >> 4;           // 0..127
        int f4 = t2 & 15;           // 0..15 float4 within row
        float4 v = ((const float4*)(emb + (size_t)sidx[p] * NC))[f4];
        *(float4*)(qs + p * 68 + f4 * 4) = v;
    }
    __syncthreads();

    // ---- output write (NCHW, coalesced) + loss partial ----
    const int lane = tid & 31, w = tid >> 5;
    float s = 0.f;
#pragma unroll
    for (int j = 0; j < 8; ++j) {
        int c = w * 8 + j;
        float* ob = out + (((size_t)bb << 6) + c) * HW + hw0;
#pragma unroll
        for (int g = 0; g < 4; ++g) {
            int p = g * 32 + lane;
            float qv = qs[p * 68 + c];
            float xv = sm[SM_XS + c * 128 + p];
            ob[p] = qv;
            float d = qv - xv;
            s = fmaf(d, d, s);
        }
    }
#pragma unroll
    for (int off = 16; off; off >>= 1) s += __shfl_xor_sync(0xffffffffu, s, off);
    float* red = sm + SM_SXS;       // reuse (sxs dead)
    if (lane == 0) red[w] = s;
    __syncthreads();
    if (tid == 0) {
        float t = 0.f;
#pragma unroll
        for (int i = 0; i < 8; ++i) t += red[i];
        atomicAdd(&g_sumsq, (double)t);
    }
}

// ---- loss + perplexity ----
__global__ void __launch_bounds__(1024) final_kernel(float* __restrict__ out, int nq) {
    __shared__ float red[32];
    int t = threadIdx.x;
    float p = (float)g_hist[t] * (1.0f / 65536.0f);
    float term = p * logf(p + 1e-10f);
#pragma unroll
    for (int off = 16; off; off >>= 1) term += __shfl_xor_sync(0xffffffffu, term, off);
    if ((t & 31) == 0) red[t >> 5] = term;
    __syncthreads();
    if (t < 32) {
        float v = red[t];
#pragma unroll
        for (int off = 16; off; off >>= 1) v += __shfl_xor_sync(0xffffffffu, v, off);
        if (t == 0) {
            float m = (float)(g_sumsq * (1.0 / (double)NELEM));
            out[nq]     = 1.25f * m;
            out[nq + 1] = expf(-v);
        }
    }
}

extern "C" void kernel_launch(void* const* d_in, const int* in_sizes, int n_in,
                              void* d_out, int out_size) {
    const float* x   = (const float*)d_in[0];
    const float* emb = (const float*)d_in[1];
    if (n_in >= 2 && in_sizes[0] == KC * NC && in_sizes[1] == NELEM) {
        const float* tmp = x; x = emb; emb = tmp;
    }
    float* out = (float*)d_out;
    int nq = out_size - 2;

    cudaFuncSetAttribute(vq_kernel, cudaFuncAttributeMaxDynamicSharedMemorySize,
                         SM_FLOATS * 4);

    // ordering: vq is the 4th launch -> ncu (-s/-c bounded) captures it
    zero_se_kernel<<<4, 256>>>(emb);
    transpose_kernel<<<32, 256>>>(emb, 0);
    transpose_kernel<<<32, 256>>>(emb, 32);
    vq_kernel<<<512, 256, SM_FLOATS * 4>>>(x, emb, out);
    final_kernel<<<1, 1024>>>(out, nq);
}